// round 12
// baseline (speedup 1.0000x reference)
#include <cuda_runtime.h>
#include <cuda_bf16.h>
#include <float.h>

#define B_    64
#define T_    256
#define V_    6625
#define S_    25
#define SX_   51
#define EW_   64              // emit row stride: 51 real + 13 NEG pads
#define NEG_  (-1e30f)
#define LOG2E_ 1.4426950408889634f
#define LN2_   0.6931471805599453f
#define NCONS 8               // consumer blocks (bid 0..7), 8 warps = 8 batches each

// Scratch (no allocations -> __device__ globals)
__device__ __align__(16) float g_emit[B_ * T_ * EW_];
__device__ float    g_loss[B_];
__device__ unsigned g_flag[B_ * T_];   // flag[(t<<6)+b]; self-resetting
__device__ unsigned g_cnt;             // completion counter; self-resetting

__device__ __forceinline__ unsigned ld_acq(const unsigned* p) {
    unsigned v;
    asm volatile("ld.acquire.gpu.global.u32 %0, [%1];" : "=r"(v) : "l"(p) : "memory");
    return v;
}
__device__ __forceinline__ void st_rel(unsigned* p, unsigned v) {
    asm volatile("st.release.gpu.global.u32 [%0], %1;" :: "l"(p), "r"(v) : "memory");
}
__device__ __forceinline__ float ex2a(float x) {
    float r; asm("ex2.approx.ftz.f32 %0, %1;" : "=f"(r) : "f"(x)); return r;
}
__device__ __forceinline__ float lg2a(float x) {
    float r; asm("lg2.approx.f32 %0, %1;" : "=f"(r) : "f"(x)); return r;
}

// ---------------------------------------------------------------------------
// Producer block: one 256-thread block per (b,t) row — the PROVEN standalone
// structure (single-pass sum-exp, __ldcs streaming, ~77-85% DRAM). t-major
// block ordering so consumers track layer-by-layer. Flag released per row.
// ---------------------------------------------------------------------------
#define K1_THREADS 256

__device__ __forceinline__ void producer(const float* __restrict__ pred,
                                         const int*   __restrict__ target) {
    const int r = blockIdx.x - NCONS;    // r = (t<<6)+b  (t-major)
    const int t = r >> 6;
    const int b = r & 63;
    const float* __restrict__ row = pred + (size_t)(b * T_ + t) * V_;
    const int tid = threadIdx.x;

    // 25 unguarded strided elements (max idx 6399 < 6625) + 1 guarded tail
    float s0 = 0.f, s1 = 0.f, s2 = 0.f, s3 = 0.f;
#pragma unroll
    for (int i = 0; i < 24; i += 4) {
        s0 += __expf(__ldcs(row + tid + (i + 0) * K1_THREADS));
        s1 += __expf(__ldcs(row + tid + (i + 1) * K1_THREADS));
        s2 += __expf(__ldcs(row + tid + (i + 2) * K1_THREADS));
        s3 += __expf(__ldcs(row + tid + (i + 3) * K1_THREADS));
    }
    s0 += __expf(__ldcs(row + tid + 24 * K1_THREADS));
    {
        int idx = tid + 25 * K1_THREADS;
        if (idx < V_) s1 += __expf(__ldcs(row + idx));
    }
    float s = (s0 + s1) + (s2 + s3);

#pragma unroll
    for (int off = 16; off > 0; off >>= 1)
        s += __shfl_down_sync(0xffffffffu, s, off);

    __shared__ float sh_s[8];
    __shared__ float sh_lse;
    const int wid = tid >> 5, lane = tid & 31;
    if (lane == 0) sh_s[wid] = s;
    __syncthreads();
    if (wid == 0) {
        s = (lane < 8) ? sh_s[lane] : 0.f;
#pragma unroll
        for (int off = 4; off > 0; off >>= 1)
            s += __shfl_down_sync(0xffffffffu, s, off);
        if (lane == 0) sh_lse = __logf(s);
    }
    __syncthreads();
    const float lse = sh_lse;

    // 51 emissions in log2 domain; cols 51..63 = NEG (sink columns)
    if (tid < EW_) {
        float val = NEG_;
        if (tid < SX_) {
            int lab = (tid & 1) ? target[b * S_ + (tid >> 1)] : 0;
            val = (row[lab] - lse) * LOG2E_;
        }
        g_emit[(size_t)(b * T_ + t) * EW_ + tid] = val;
    }
    __syncthreads();
    if (tid == 0) { __threadfence(); st_rel(&g_flag[r], 1u); }
}

// ---------------------------------------------------------------------------
// Consumer block: 8 warps, one batch per warp (blocks 0..7 -> 64 batches),
// resident from wave 1. Validated R5 structure: direct-L2 emit loads, per-row
// flag spin with backoff, prefetch e(t+1) + flag(t+2); log2-domain branch-free
// recursion (lane31 NEG sink, additive skip bias). Flags reset on consume.
// Batch mean folded in (last-finishing warp reduces). Needs ZERO smem.
// ---------------------------------------------------------------------------
__device__ __forceinline__ void consumer(const int* __restrict__ target,
                                         const int* __restrict__ length,
                                         float* __restrict__ out) {
    const int b = (blockIdx.x << 3) + (threadIdx.x >> 5);   // 0..63
    const int lane = threadIdx.x & 31;
    const int rsrc = (lane + 31) & 31;   // lane-1; lane0 -> lane31 (NEG sink)

    float sbias = -2e30f;                // additive mask for the skip path
    if (lane > 0 && lane < 25)
        if (target[b * S_ + lane] != target[b * S_ + lane - 1]) sbias = 0.f;

    const float2* __restrict__ ep =
        reinterpret_cast<const float2*>(g_emit) + (size_t)(b * T_) * (EW_ / 2) + lane;
    unsigned* fl = g_flag + b;
    volatile unsigned* flv = fl;

    // t = 0
    while (ld_acq(fl + 0) == 0) { __nanosleep(100); }
    flv[0] = 0;
    float2 e0 = __ldcg(ep);
    float lo = (lane == 0) ? e0.x : NEG_;
    float hi = (lane == 0) ? e0.y : NEG_;

    // t = 1 data
    while (ld_acq(fl + 64) == 0) { __nanosleep(100); }
    flv[64] = 0;
    float2 ecur = __ldcg(ep + (EW_ / 2));
    unsigned fnxt = ld_acq(fl + 128);

#pragma unroll 1
    for (int t = 1; t < T_; ++t) {
        float2 enxt = make_float2(NEG_, NEG_);
        if (t + 1 < T_) {
            const int i = (t + 1) << 6;
            if (fnxt == 0) { while (ld_acq(fl + i) == 0) { __nanosleep(40); } }
            flv[i] = 0;
            enxt = __ldcg(ep + (size_t)(t + 1) * (EW_ / 2));
            fnxt = (t + 2 < T_) ? ld_acq(fl + ((t + 2) << 6)) : 1u;
        }
        // recursion step (overlaps with the enxt load)
        float p   = __shfl_sync(0xffffffffu, hi, rsrc);
        float m2  = fmaxf(lo, p);
        float nlo = m2 + lg2a(ex2a(lo - m2) + ex2a(p - m2)) + ecur.x;
        float a3  = p + sbias;
        float m3  = fmaxf(hi, fmaxf(lo, a3));
        float nhi = m3 + lg2a(ex2a(hi - m3) + ex2a(lo - m3)
                            + ex2a(a3 - m3)) + ecur.y;
        lo = nlo; hi = nhi;
        ecur = enxt;
    }

    // ll = logsumexp(alpha[2L-1], alpha[2L])  (log2 -> natural at the end)
    const int L = length[b];
    float ah = __shfl_sync(0xffffffffu, hi, L - 1);
    float al = __shfl_sync(0xffffffffu, lo, L);

    int cdone = 0;
    if (lane == 0) {
        float m   = fmaxf(ah, al);
        float ll  = (m + log2f(exp2f(ah - m) + exp2f(al - m))) * LN2_;
        float loss = -ll;
        if (!isfinite(loss)) loss = 0.f;
        g_loss[b] = loss / (float)L;
        __threadfence();
        cdone = (int)atomicAdd(&g_cnt, 1u);
    }
    cdone = __shfl_sync(0xffffffffu, cdone, 0);

    if (cdone == B_ - 1) {               // last finishing warp: batch mean
        __threadfence();
        float v = g_loss[lane] + g_loss[lane + 32];
#pragma unroll
        for (int off = 16; off > 0; off >>= 1)
            v += __shfl_down_sync(0xffffffffu, v, off);
        if (lane == 0) {
            out[0] = v / (float)B_;
            atomicExch(&g_cnt, 0u);      // reset for next graph replay
        }
    }
}

// ---------------------------------------------------------------------------
// Unified kernel. __launch_bounds__(256, 5) => 51-reg budget: forces ptxas to
// compile the producer like the standalone (38-45 regs, front-batched loads)
// instead of the 32-reg spill that killed R4/R5/R6.
// ---------------------------------------------------------------------------
__global__ __launch_bounds__(256, 5)
void ctc_fused_kernel(const float* __restrict__ pred,
                      const int*   __restrict__ target,
                      const int*   __restrict__ length,
                      float* __restrict__ out) {
    if (blockIdx.x >= NCONS) producer(pred, target);
    else                     consumer(target, length, out);
}

extern "C" void kernel_launch(void* const* d_in, const int* in_sizes, int n_in,
                              void* d_out, int out_size) {
    const float* pred   = (const float*)d_in[0];
    const int*   target = (const int*)d_in[1];
    const int*   length = (const int*)d_in[2];
    float* out = (float*)d_out;

    ctc_fused_kernel<<<NCONS + B_ * T_, 256>>>(pred, target, length, out);
}